// round 15
// baseline (speedup 1.0000x reference)
#include <cuda_runtime.h>
#include <cuda_bf16.h>
#include <stdint.h>
#include <math.h>

#define BATCH 8192
#define DIM 64
#define TILE 128
#define NT (BATCH/TILE)          /* 64 row/col tiles   */
#define NTRI (NT*(NT+1)/2)       /* 2080 triangular tiles */

// smem: A tile [128 rows x 80B], B tile same, reduce scratch.
// 64B fp8 data + 16B pad per row: lane->bank = (gid*20 + tig) mod 32, all distinct.
#define SROWB 80
#define SM_A   0
#define SM_B   (128*SROWB)
#define SM_RED (2*128*SROWB)
#define SMEM_BYTES (SM_RED + 64)

// Scratch: normalized embeddings quantized to e4m3 + accumulators.
__device__ unsigned char g_Xu[BATCH*DIM];
__device__ unsigned char g_Xp[BATCH*DIM];
__device__ double g_acc[3];          // [0] align dots, [1] Su total, [2] Sp total
__device__ unsigned int g_cnt;       // completed gram blocks (reset each run)

__device__ __forceinline__ float fast_ex2(float x) {
    float r; asm("ex2.approx.ftz.f32 %0, %1;" : "=f"(r) : "f"(x)); return r;
}
// pack two fp32 -> e4m3x2 (byte0 = x0, byte1 = x1)
__device__ __forceinline__ unsigned int pack_e4m3x2(float x0, float x1) {
    unsigned int p;
    asm("{ .reg .b16 lo;\n\t"
        "cvt.rn.satfinite.e4m3x2.f32 lo, %1, %2;\n\t"
        "cvt.u32.u16 %0, lo; }" : "=r"(p) : "f"(x1), "f"(x0));
    return p;
}

// One warp per batch row: gather, fp32 normalize, quantize e4m3, alignment dot fp32.
__global__ void gather_normalize_kernel(const int* __restrict__ uid,
                                        const int* __restrict__ pid,
                                        const float* __restrict__ utab,
                                        const float* __restrict__ itab) {
    int row  = blockIdx.x * 8 + (threadIdx.x >> 5);
    int lane = threadIdx.x & 31;
    const float* up = utab + (size_t)uid[row] * DIM;
    const float* pp = itab + (size_t)pid[row] * DIM;
    // adjacent components per lane so the e4m3 pair is contiguous
    float u0 = up[2*lane], u1 = up[2*lane+1];
    float p0 = pp[2*lane], p1 = pp[2*lane+1];
    float su = u0*u0 + u1*u1;
    float sp = p0*p0 + p1*p1;
#pragma unroll
    for (int o = 16; o; o >>= 1) {
        su += __shfl_xor_sync(0xffffffffu, su, o);
        sp += __shfl_xor_sync(0xffffffffu, sp, o);
    }
    float ru = rsqrtf(su), rp = rsqrtf(sp);
    u0 *= ru; u1 *= ru; p0 *= rp; p1 *= rp;
    *(unsigned short*)(g_Xu + (size_t)row*DIM + 2*lane) = (unsigned short)pack_e4m3x2(u0, u1);
    *(unsigned short*)(g_Xp + (size_t)row*DIM + 2*lane) = (unsigned short)pack_e4m3x2(p0, p1);
    float d = u0*p0 + u1*p1;
#pragma unroll
    for (int o = 16; o; o >>= 1) d += __shfl_xor_sync(0xffffffffu, d, o);
    if (lane == 0) atomicAdd(&g_acc[0], (double)d);
}

// Triangular-tiled Gram sum via mma.sync m16n8k32 e4m3 -> f32.
// Block: D[128,128] = A[128,64] @ B[128,64]^T; epilogue sums exp(4*sim-4).
// Warp tile 32x64: 2 m-atoms x 8 n-atoms, K=64 in 2 k32-steps.
// Last finishing block computes the final scalar and resets accumulators.
__global__ void __launch_bounds__(256, 2) gram_mma_kernel(float* __restrict__ out) {
    extern __shared__ char smem[];
    int tid = threadIdx.x, wid = tid >> 5, lane = tid & 31;
    int gid = lane >> 2, tig = lane & 3;

    const unsigned char* X = (blockIdx.y == 0) ? g_Xu : g_Xp;
    int b = blockIdx.x;
    int ti = (int)((2.0*NT + 1.0 - sqrt((2.0*NT+1.0)*(2.0*NT+1.0) - 8.0*(double)b)) * 0.5);
    while (ti*(2*NT - ti + 1)/2 > b) ti--;
    while ((ti+1)*(2*NT - ti)/2 <= b) ti++;
    int tj = ti + (b - ti*(2*NT - ti + 1)/2);

    // Load both 128x64 fp8 tiles (8KB each, contiguous). 64B row = 4 x 16B chunks.
    const uint4* A4 = (const uint4*)(X + (size_t)ti*TILE*DIM);
    const uint4* B4 = (const uint4*)(X + (size_t)tj*TILE*DIM);
#pragma unroll
    for (int i = 0; i < 2; i++) {
        int idx = tid + i*256;            // 0..511 16B chunks
        int dst = (idx >> 2)*SROWB + (idx & 3)*16;
        *(uint4*)(smem + SM_A + dst) = A4[idx];
        *(uint4*)(smem + SM_B + dst) = B4[idx];
    }
    __syncthreads();

    int warpRow = (wid & 3) * 32;         // 4 warps over 128 rows
    int warpCol = (wid >> 2) * 64;        // 2 warps over 128 cols

    float d[2][8][4];
#pragma unroll
    for (int am = 0; am < 2; am++)
#pragma unroll
        for (int na = 0; na < 8; na++)
#pragma unroll
            for (int e = 0; e < 4; e++) d[am][na][e] = 0.f;

#pragma unroll
    for (int ks = 0; ks < 2; ks++) {
        int kb = ks*32 + tig*4;           // this thread's 4-byte k group
        unsigned int a_[2][4];
#pragma unroll
        for (int am = 0; am < 2; am++) {
            const char* base = smem + SM_A + (warpRow + am*16 + gid)*SROWB + kb;
            a_[am][0] = *(const unsigned int*)(base);
            a_[am][1] = *(const unsigned int*)(base + 8*SROWB);
            a_[am][2] = *(const unsigned int*)(base + 16);
            a_[am][3] = *(const unsigned int*)(base + 8*SROWB + 16);
        }
        unsigned int b_[8][2];
#pragma unroll
        for (int na = 0; na < 8; na++) {
            const char* base = smem + SM_B + (warpCol + na*8 + gid)*SROWB + kb;
            b_[na][0] = *(const unsigned int*)(base);
            b_[na][1] = *(const unsigned int*)(base + 16);
        }
#pragma unroll
        for (int am = 0; am < 2; am++)
#pragma unroll
            for (int na = 0; na < 8; na++)
                asm("mma.sync.aligned.m16n8k32.row.col.f32.e4m3.e4m3.f32 "
                    "{%0,%1,%2,%3}, {%4,%5,%6,%7}, {%8,%9}, {%0,%1,%2,%3};"
                    : "+f"(d[am][na][0]), "+f"(d[am][na][1]),
                      "+f"(d[am][na][2]), "+f"(d[am][na][3])
                    : "r"(a_[am][0]), "r"(a_[am][1]), "r"(a_[am][2]), "r"(a_[am][3]),
                      "r"(b_[na][0]), "r"(b_[na][1]));
    }

    // Epilogue: sum exp(4*sim-4) = exp2(sim*K2 - K2).
    const float K2 = 5.770780163555852f;   // 4*log2(e)
    float s0 = 0.f, s1 = 0.f, s2 = 0.f, s3 = 0.f;
#pragma unroll
    for (int am = 0; am < 2; am++)
#pragma unroll
        for (int na = 0; na < 8; na++) {
            s0 += fast_ex2(fmaf(d[am][na][0], K2, -K2));
            s1 += fast_ex2(fmaf(d[am][na][1], K2, -K2));
            s2 += fast_ex2(fmaf(d[am][na][2], K2, -K2));
            s3 += fast_ex2(fmaf(d[am][na][3], K2, -K2));
        }
    float s = (s0 + s1) + (s2 + s3);
    if (ti != tj) s *= 2.0f;

#pragma unroll
    for (int o = 16; o; o >>= 1) s += __shfl_xor_sync(0xffffffffu, s, o);
    if (lane == 0) *(volatile float*)(smem + SM_RED + (wid<<2)) = s;
    __syncthreads();
    if (tid == 0) {
        volatile float* red = (volatile float*)(smem + SM_RED);
        float t = ((red[0] + red[1]) + (red[2] + red[3]))
                + ((red[4] + red[5]) + (red[6] + red[7]));
        atomicAdd(&g_acc[1 + blockIdx.y], (double)t);
        __threadfence();
        unsigned int done = atomicAdd(&g_cnt, 1u);
        if (done == 2u*NTRI - 1u) {
            // Last block: finalize + reset state for next graph replay.
            __threadfence();
            double a0 = *(volatile double*)&g_acc[0];
            double a1 = *(volatile double*)&g_acc[1];
            double a2 = *(volatile double*)&g_acc[2];
            double n = (double)BATCH;
            double align = 2.0 - 2.0 * a0 / n;
            double denom = n * (n - 1.0);
            double uu = log((a1 - n) / denom);
            double vv = log((a2 - n) / denom);
            out[0] = (float)(align + 0.5 * (uu + vv));   // GAMMA = 1
            *(volatile double*)&g_acc[0] = 0.0;
            *(volatile double*)&g_acc[1] = 0.0;
            *(volatile double*)&g_acc[2] = 0.0;
            __threadfence();
            *(volatile unsigned int*)&g_cnt = 0u;
        }
    }
}

extern "C" void kernel_launch(void* const* d_in, const int* in_sizes, int n_in,
                              void* d_out, int out_size) {
    (void)in_sizes; (void)n_in; (void)out_size;
    const int*   uid  = (const int*)d_in[0];
    const int*   pid  = (const int*)d_in[1];
    /* d_in[2] = neg_id, unused by the reference loss */
    const float* utab = (const float*)d_in[3];
    const float* itab = (const float*)d_in[4];
    float* out = (float*)d_out;

    cudaFuncSetAttribute(gram_mma_kernel,
                         cudaFuncAttributeMaxDynamicSharedMemorySize, SMEM_BYTES);

    gather_normalize_kernel<<<BATCH/8, 256>>>(uid, pid, utab, itab);
    dim3 grid(NTRI, 2);
    gram_mma_kernel<<<grid, 256, SMEM_BYTES>>>(out);
}

// round 16
// speedup vs baseline: 1.2987x; 1.2987x over previous
#include <cuda_runtime.h>
#include <cuda_bf16.h>
#include <stdint.h>
#include <math.h>

#define BATCH 8192
#define DIM 64
#define TILE 128
#define NT (BATCH/TILE)          /* 64 row/col tiles   */
#define NTRI (NT*(NT+1)/2)       /* 2080 triangular tiles */

// smem: A tile [128 rows x 144B], B tile same, then reduce scratch.
#define SROWB 144                /* 128B data + 16B pad; 16B chunks aligned, LDS conflict-free */
#define SM_A   0
#define SM_B   (128*SROWB)
#define SM_RED (2*128*SROWB)
#define SMEM_BYTES (SM_RED + 64)

__device__ __nv_bfloat16 g_Xu[BATCH*DIM];
__device__ __nv_bfloat16 g_Xp[BATCH*DIM];
__device__ double g_acc[3];          // [0] align dots, [1] Su total, [2] Sp total
__device__ unsigned int g_cnt;       // completed gram blocks (reset each run)

__device__ __forceinline__ float fast_ex2(float x) {
    float r; asm("ex2.approx.ftz.f32 %0, %1;" : "=f"(r) : "f"(x)); return r;
}

// One warp per batch row: gather, fp32 normalize, store bf16, alignment dot fp32.
__global__ void gather_normalize_kernel(const int* __restrict__ uid,
                                        const int* __restrict__ pid,
                                        const float* __restrict__ utab,
                                        const float* __restrict__ itab) {
    int row  = blockIdx.x * 8 + (threadIdx.x >> 5);
    int lane = threadIdx.x & 31;
    const float* up = utab + (size_t)uid[row] * DIM;
    const float* pp = itab + (size_t)pid[row] * DIM;
    float u0 = up[lane], u1 = up[lane + 32];
    float p0 = pp[lane], p1 = pp[lane + 32];
    float su = u0*u0 + u1*u1;
    float sp = p0*p0 + p1*p1;
#pragma unroll
    for (int o = 16; o; o >>= 1) {
        su += __shfl_xor_sync(0xffffffffu, su, o);
        sp += __shfl_xor_sync(0xffffffffu, sp, o);
    }
    float ru = rsqrtf(su), rp = rsqrtf(sp);
    u0 *= ru; u1 *= ru; p0 *= rp; p1 *= rp;
    g_Xu[row*DIM + lane]      = __float2bfloat16(u0);
    g_Xu[row*DIM + lane + 32] = __float2bfloat16(u1);
    g_Xp[row*DIM + lane]      = __float2bfloat16(p0);
    g_Xp[row*DIM + lane + 32] = __float2bfloat16(p1);
    float d = u0*p0 + u1*p1;
#pragma unroll
    for (int o = 16; o; o >>= 1) d += __shfl_xor_sync(0xffffffffu, d, o);
    if (lane == 0) atomicAdd(&g_acc[0], (double)d);
}

// Triangular-tiled Gram sum via mma.sync (HMMA, bf16 x bf16 -> f32).
// Block: D[128,128] = A[128,64] @ B[128,64]^T; epilogue sums exp(4*sim-4).
// Warp tile 32x64: 2 m-atoms x 8 n-atoms of m16n8k16, K=64 in 4 k-steps.
// Last finishing block computes the final scalar and resets accumulators.
__global__ void __launch_bounds__(256, 2) gram_mma_kernel(float* __restrict__ out) {
    extern __shared__ char smem[];
    int tid = threadIdx.x, wid = tid >> 5, lane = tid & 31;
    int gid = lane >> 2, tig = lane & 3;                 // fragment coords

    const __nv_bfloat16* X = (blockIdx.y == 0) ? g_Xu : g_Xp;
    int b = blockIdx.x;
    int ti = (int)((2.0*NT + 1.0 - sqrt((2.0*NT+1.0)*(2.0*NT+1.0) - 8.0*(double)b)) * 0.5);
    while (ti*(2*NT - ti + 1)/2 > b) ti--;
    while ((ti+1)*(2*NT - ti)/2 <= b) ti++;
    int tj = ti + (b - ti*(2*NT - ti + 1)/2);

    // Load both 128x64 bf16 tiles (16KB each, contiguous) into padded smem.
    const uint4* A4 = (const uint4*)(X + (size_t)ti*TILE*DIM);
    const uint4* B4 = (const uint4*)(X + (size_t)tj*TILE*DIM);
#pragma unroll
    for (int i = 0; i < 4; i++) {
        int idx = tid + i*256;            // 0..1023 16B chunks
        int dst = (idx >> 3)*SROWB + (idx & 7)*16;
        *(uint4*)(smem + SM_A + dst) = A4[idx];
        *(uint4*)(smem + SM_B + dst) = B4[idx];
    }
    __syncthreads();

    int warpRow = (wid & 3) * 32;         // 4 warps over 128 rows
    int warpCol = (wid >> 2) * 64;        // 2 warps over 128 cols

    float d[2][8][4];
#pragma unroll
    for (int am = 0; am < 2; am++)
#pragma unroll
        for (int na = 0; na < 8; na++)
#pragma unroll
            for (int e = 0; e < 4; e++) d[am][na][e] = 0.f;

#pragma unroll
    for (int ks = 0; ks < 4; ks++) {
        int kb = ks*32 + tig*4;           // byte offset of this thread's k pair
        unsigned int a_[2][4];
#pragma unroll
        for (int am = 0; am < 2; am++) {
            const char* base = smem + SM_A + (warpRow + am*16 + gid)*SROWB + kb;
            a_[am][0] = *(const unsigned int*)(base);
            a_[am][1] = *(const unsigned int*)(base + 8*SROWB);
            a_[am][2] = *(const unsigned int*)(base + 16);
            a_[am][3] = *(const unsigned int*)(base + 8*SROWB + 16);
        }
        unsigned int b_[8][2];
#pragma unroll
        for (int na = 0; na < 8; na++) {
            const char* base = smem + SM_B + (warpCol + na*8 + gid)*SROWB + kb;
            b_[na][0] = *(const unsigned int*)(base);
            b_[na][1] = *(const unsigned int*)(base + 16);
        }
#pragma unroll
        for (int am = 0; am < 2; am++)
#pragma unroll
            for (int na = 0; na < 8; na++)
                asm("mma.sync.aligned.m16n8k16.row.col.f32.bf16.bf16.f32 "
                    "{%0,%1,%2,%3}, {%4,%5,%6,%7}, {%8,%9}, {%0,%1,%2,%3};"
                    : "+f"(d[am][na][0]), "+f"(d[am][na][1]),
                      "+f"(d[am][na][2]), "+f"(d[am][na][3])
                    : "r"(a_[am][0]), "r"(a_[am][1]), "r"(a_[am][2]), "r"(a_[am][3]),
                      "r"(b_[na][0]), "r"(b_[na][1]));
    }

    // Epilogue: sum exp(4*sim-4) = exp2(sim*K2 - K2).
    const float K2 = 5.770780163555852f;   // 4*log2(e)
    float s0 = 0.f, s1 = 0.f, s2 = 0.f, s3 = 0.f;
#pragma unroll
    for (int am = 0; am < 2; am++)
#pragma unroll
        for (int na = 0; na < 8; na++) {
            s0 += fast_ex2(fmaf(d[am][na][0], K2, -K2));
            s1 += fast_ex2(fmaf(d[am][na][1], K2, -K2));
            s2 += fast_ex2(fmaf(d[am][na][2], K2, -K2));
            s3 += fast_ex2(fmaf(d[am][na][3], K2, -K2));
        }
    float s = (s0 + s1) + (s2 + s3);
    if (ti != tj) s *= 2.0f;

#pragma unroll
    for (int o = 16; o; o >>= 1) s += __shfl_xor_sync(0xffffffffu, s, o);
    if (lane == 0) *(volatile float*)(smem + SM_RED + (wid<<2)) = s;
    __syncthreads();
    if (tid == 0) {
        volatile float* red = (volatile float*)(smem + SM_RED);
        float t = ((red[0] + red[1]) + (red[2] + red[3]))
                + ((red[4] + red[5]) + (red[6] + red[7]));
        atomicAdd(&g_acc[1 + blockIdx.y], (double)t);
        __threadfence();
        unsigned int done = atomicAdd(&g_cnt, 1u);
        if (done == 2u*NTRI - 1u) {
            // Last block: finalize + reset state for next graph replay.
            __threadfence();
            double a0 = *(volatile double*)&g_acc[0];
            double a1 = *(volatile double*)&g_acc[1];
            double a2 = *(volatile double*)&g_acc[2];
            double n = (double)BATCH;
            double align = 2.0 - 2.0 * a0 / n;
            double denom = n * (n - 1.0);
            double uu = log((a1 - n) / denom);
            double vv = log((a2 - n) / denom);
            out[0] = (float)(align + 0.5 * (uu + vv));   // GAMMA = 1
            *(volatile double*)&g_acc[0] = 0.0;
            *(volatile double*)&g_acc[1] = 0.0;
            *(volatile double*)&g_acc[2] = 0.0;
            __threadfence();
            *(volatile unsigned int*)&g_cnt = 0u;
        }
    }
}

extern "C" void kernel_launch(void* const* d_in, const int* in_sizes, int n_in,
                              void* d_out, int out_size) {
    (void)in_sizes; (void)n_in; (void)out_size;
    const int*   uid  = (const int*)d_in[0];
    const int*   pid  = (const int*)d_in[1];
    /* d_in[2] = neg_id, unused by the reference loss */
    const float* utab = (const float*)d_in[3];
    const float* itab = (const float*)d_in[4];
    float* out = (float*)d_out;

    cudaFuncSetAttribute(gram_mma_kernel,
                         cudaFuncAttributeMaxDynamicSharedMemorySize, SMEM_BYTES);

    gather_normalize_kernel<<<BATCH/8, 256>>>(uid, pid, utab, itab);
    dim3 grid(NTRI, 2);
    gram_mma_kernel<<<grid, 256, SMEM_BYTES>>>(out);
}

// round 17
// speedup vs baseline: 1.3680x; 1.0534x over previous
#include <cuda_runtime.h>
#include <cuda_bf16.h>
#include <stdint.h>
#include <math.h>

#define BATCH 8192
#define DIM 64
#define TILE2 64
#define NT2 (BATCH/TILE2)          /* 128 tiles of 64 rows */
#define NTRI2 (NT2*(NT2+1)/2)      /* 8256 triangular tiles */

// smem: A tile [64 rows x 144B], B tile same, reduce scratch.
#define SROWB 144                  /* 128B data + 16B pad; LDS conflict-free */
#define SM_A   0
#define SM_B   (64*SROWB)
#define SM_RED (2*64*SROWB)
#define SMEM_BYTES (SM_RED + 32)

__device__ __nv_bfloat16 g_Xu[BATCH*DIM];
__device__ __nv_bfloat16 g_Xp[BATCH*DIM];
__device__ double g_acc[3];   // [0] align dots, [1] Su total, [2] Sp total

__device__ __forceinline__ float fast_ex2(float x) {
    float r; asm("ex2.approx.ftz.f32 %0, %1;" : "=f"(r) : "f"(x)); return r;
}

__global__ void zero_acc_kernel() {
    if (threadIdx.x < 3) g_acc[threadIdx.x] = 0.0;
}

// One warp per batch row: gather, fp32 normalize, store bf16, alignment dot fp32.
__global__ void gather_normalize_kernel(const int* __restrict__ uid,
                                        const int* __restrict__ pid,
                                        const float* __restrict__ utab,
                                        const float* __restrict__ itab) {
    int row  = blockIdx.x * 8 + (threadIdx.x >> 5);
    int lane = threadIdx.x & 31;
    const float* up = utab + (size_t)uid[row] * DIM;
    const float* pp = itab + (size_t)pid[row] * DIM;
    float u0 = up[lane], u1 = up[lane + 32];
    float p0 = pp[lane], p1 = pp[lane + 32];
    float su = u0*u0 + u1*u1;
    float sp = p0*p0 + p1*p1;
#pragma unroll
    for (int o = 16; o; o >>= 1) {
        su += __shfl_xor_sync(0xffffffffu, su, o);
        sp += __shfl_xor_sync(0xffffffffu, sp, o);
    }
    float ru = rsqrtf(su), rp = rsqrtf(sp);
    u0 *= ru; u1 *= ru; p0 *= rp; p1 *= rp;
    g_Xu[row*DIM + lane]      = __float2bfloat16(u0);
    g_Xu[row*DIM + lane + 32] = __float2bfloat16(u1);
    g_Xp[row*DIM + lane]      = __float2bfloat16(p0);
    g_Xp[row*DIM + lane + 32] = __float2bfloat16(p1);
    float d = u0*p0 + u1*p1;
#pragma unroll
    for (int o = 16; o; o >>= 1) d += __shfl_xor_sync(0xffffffffu, d, o);
    if (lane == 0) atomicAdd(&g_acc[0], (double)d);
}

// Triangular-tiled Gram sum via mma.sync (HMMA, bf16 x bf16 -> f32).
// Block (128 thr): D[64,64] = A[64,64] @ B[64,64]^T; epilogue sums exp(4*sim-4).
// Warp tile 32x32: 2 m-atoms x 4 n-atoms of m16n8k16, K=64 in 4 k-steps.
// 32 accум floats/thread -> ~80 regs -> 6 CTAs/SM (24 warps) vs old 16.
__global__ void __launch_bounds__(128, 6) gram_mma_kernel() {
    extern __shared__ char smem[];
    int tid = threadIdx.x, wid = tid >> 5, lane = tid & 31;
    int gid = lane >> 2, tig = lane & 3;                 // fragment coords

    const __nv_bfloat16* X = (blockIdx.y == 0) ? g_Xu : g_Xp;
    int b = blockIdx.x;
    int ti = (int)((2.0*NT2 + 1.0 - sqrt((2.0*NT2+1.0)*(2.0*NT2+1.0) - 8.0*(double)b)) * 0.5);
    while (ti*(2*NT2 - ti + 1)/2 > b) ti--;
    while ((ti+1)*(2*NT2 - ti)/2 <= b) ti++;
    int tj = ti + (b - ti*(2*NT2 - ti + 1)/2);

    // Load both 64x64 bf16 tiles (8KB each, contiguous) into padded smem.
    const uint4* A4 = (const uint4*)(X + (size_t)ti*TILE2*DIM);
    const uint4* B4 = (const uint4*)(X + (size_t)tj*TILE2*DIM);
#pragma unroll
    for (int i = 0; i < 4; i++) {
        int idx = tid + i*128;            // 0..511 16B chunks, 8 per row
        int dst = (idx >> 3)*SROWB + (idx & 7)*16;
        *(uint4*)(smem + SM_A + dst) = A4[idx];
        *(uint4*)(smem + SM_B + dst) = B4[idx];
    }
    __syncthreads();

    int warpRow = (wid & 1) * 32;         // 2 warps over 64 rows
    int warpCol = (wid >> 1) * 32;        // 2 warps over 64 cols

    float d[2][4][4];
#pragma unroll
    for (int am = 0; am < 2; am++)
#pragma unroll
        for (int na = 0; na < 4; na++)
#pragma unroll
            for (int e = 0; e < 4; e++) d[am][na][e] = 0.f;

#pragma unroll
    for (int ks = 0; ks < 4; ks++) {
        int kb = ks*32 + tig*4;           // byte offset of this thread's k pair
        unsigned int a_[2][4];
#pragma unroll
        for (int am = 0; am < 2; am++) {
            const char* base = smem + SM_A + (warpRow + am*16 + gid)*SROWB + kb;
            a_[am][0] = *(const unsigned int*)(base);
            a_[am][1] = *(const unsigned int*)(base + 8*SROWB);
            a_[am][2] = *(const unsigned int*)(base + 16);
            a_[am][3] = *(const unsigned int*)(base + 8*SROWB + 16);
        }
        unsigned int b_[4][2];
#pragma unroll
        for (int na = 0; na < 4; na++) {
            const char* base = smem + SM_B + (warpCol + na*8 + gid)*SROWB + kb;
            b_[na][0] = *(const unsigned int*)(base);
            b_[na][1] = *(const unsigned int*)(base + 16);
        }
#pragma unroll
        for (int am = 0; am < 2; am++)
#pragma unroll
            for (int na = 0; na < 4; na++)
                asm("mma.sync.aligned.m16n8k16.row.col.f32.bf16.bf16.f32 "
                    "{%0,%1,%2,%3}, {%4,%5,%6,%7}, {%8,%9}, {%0,%1,%2,%3};"
                    : "+f"(d[am][na][0]), "+f"(d[am][na][1]),
                      "+f"(d[am][na][2]), "+f"(d[am][na][3])
                    : "r"(a_[am][0]), "r"(a_[am][1]), "r"(a_[am][2]), "r"(a_[am][3]),
                      "r"(b_[na][0]), "r"(b_[na][1]));
    }

    // Epilogue: sum exp(4*sim-4) = exp2(sim*K2 - K2).
    const float K2 = 5.770780163555852f;   // 4*log2(e)
    float s0 = 0.f, s1 = 0.f, s2 = 0.f, s3 = 0.f;
#pragma unroll
    for (int am = 0; am < 2; am++)
#pragma unroll
        for (int na = 0; na < 4; na++) {
            s0 += fast_ex2(fmaf(d[am][na][0], K2, -K2));
            s1 += fast_ex2(fmaf(d[am][na][1], K2, -K2));
            s2 += fast_ex2(fmaf(d[am][na][2], K2, -K2));
            s3 += fast_ex2(fmaf(d[am][na][3], K2, -K2));
        }
    float s = (s0 + s1) + (s2 + s3);
    if (ti != tj) s *= 2.0f;

#pragma unroll
    for (int o = 16; o; o >>= 1) s += __shfl_xor_sync(0xffffffffu, s, o);
    if (lane == 0) *(volatile float*)(smem + SM_RED + (wid<<2)) = s;
    __syncthreads();
    if (tid == 0) {
        volatile float* red = (volatile float*)(smem + SM_RED);
        float t = (red[0] + red[1]) + (red[2] + red[3]);
        atomicAdd(&g_acc[1 + blockIdx.y], (double)t);
    }
}

__global__ void finalize_kernel(float* out) {
    double n = (double)BATCH;
    double align = 2.0 - 2.0 * g_acc[0] / n;
    double denom = n * (n - 1.0);
    double uu = log((g_acc[1] - n) / denom);
    double vv = log((g_acc[2] - n) / denom);
    out[0] = (float)(align + 0.5 * (uu + vv));   // GAMMA = 1
}

extern "C" void kernel_launch(void* const* d_in, const int* in_sizes, int n_in,
                              void* d_out, int out_size) {
    (void)in_sizes; (void)n_in; (void)out_size;
    const int*   uid  = (const int*)d_in[0];
    const int*   pid  = (const int*)d_in[1];
    /* d_in[2] = neg_id, unused by the reference loss */
    const float* utab = (const float*)d_in[3];
    const float* itab = (const float*)d_in[4];
    float* out = (float*)d_out;

    cudaFuncSetAttribute(gram_mma_kernel,
                         cudaFuncAttributeMaxDynamicSharedMemorySize, SMEM_BYTES);

    zero_acc_kernel<<<1, 32>>>();
    gather_normalize_kernel<<<BATCH/8, 256>>>(uid, pid, utab, itab);
    dim3 grid(NTRI2, 2);
    gram_mma_kernel<<<grid, 128, SMEM_BYTES>>>();
    finalize_kernel<<<1, 1>>>(out);
}